// round 11
// baseline (speedup 1.0000x reference)
#include <cuda_runtime.h>
#include <cuda_fp16.h>
#include <math.h>
#include <stdint.h>

#define T_TOK 32768
#define H_DIM 768
#define C_CH  3
#define KFD   256
#define M_MLP 3072
#define LN_EPS 1e-6f

// ---- GEMM tiling (fp16 mma.sync m16n8k16, swizzled smem, ldmatrix) ----
#define GBM 128
#define GBN 128
#define BKH 64                     // halves per K-tile (128B rows)
#define STAGES 3
#define A_BYTES (GBM * 128)        // 16384
#define B_BYTES (GBN * 128)        // 16384
#define STAGE_BYTES (A_BYTES + B_BYTES)     // 32768
#define SMEMG_BYTES (STAGES * STAGE_BYTES)  // 98304

// Scratch (device globals; no allocations anywhere).
__device__ __align__(16) __half g_s1[(size_t)T_TOK * M_MLP];  // qkv [T,2304] then act [T,3072]
__device__ __align__(16) __half g_s2[(size_t)T_TOK * H_DIM];  // h / ctx / y
__device__ __align__(16) float  g_xr[(size_t)T_TOK * H_DIM];
// transposed fp16 weights (K-major rows [N,K]):
#define WOFF_QKV 0
#define WOFF_OUT 589824
#define WOFF_W1  655360
#define WOFF_W2  3014656
__device__ __align__(16) __half g_w[5373952];

// ---------------------------------------------------------------- helpers
__device__ __forceinline__ float gelu_exact(float x)
{
    return 0.5f * x * (1.0f + erff(x * 0.70710678118654752f));
}

__device__ __forceinline__ void cp16(uint32_t dst_smem, const void* src)
{
    asm volatile("cp.async.cg.shared.global [%0], [%1], 16;\n" :: "r"(dst_smem), "l"(src));
}

__device__ __forceinline__ void ldsm4(uint32_t* r, uint32_t addr)
{
    asm volatile("ldmatrix.sync.aligned.m8n8.x4.shared.b16 {%0,%1,%2,%3}, [%4];"
                 : "=r"(r[0]), "=r"(r[1]), "=r"(r[2]), "=r"(r[3]) : "r"(addr));
}

__device__ __forceinline__ void mma_f16(float* d, const uint32_t* a,
                                        uint32_t b0, uint32_t b1)
{
    asm volatile(
        "mma.sync.aligned.m16n8k16.row.col.f32.f16.f16.f32 "
        "{%0,%1,%2,%3}, {%4,%5,%6,%7}, {%8,%9}, {%0,%1,%2,%3};\n"
        : "+f"(d[0]), "+f"(d[1]), "+f"(d[2]), "+f"(d[3])
        : "r"(a[0]), "r"(a[1]), "r"(a[2]), "r"(a[3]), "r"(b0), "r"(b1));
}

// ---------------------------------------------------------------- transpose+half
__global__ void transpose_h_kernel(const float* __restrict__ in,
                                   __half* __restrict__ out, int K, int N)
{
    __shared__ float t[32][33];
    size_t bo = (size_t)blockIdx.z * K * N;
    in += bo;
    out += bo;
    int k0 = blockIdx.y * 32, n0 = blockIdx.x * 32;
    int x = threadIdx.x, y = threadIdx.y;
#pragma unroll
    for (int i = 0; i < 32; i += 8)
        t[y + i][x] = in[(size_t)(k0 + y + i) * N + n0 + x];
    __syncthreads();
#pragma unroll
    for (int i = 0; i < 32; i += 8)
        out[(size_t)(n0 + y + i) * K + k0 + x] = __float2half_rn(t[x][y + i]);
}

// ---------------------------------------------------------------- LayerNorm -> half
// vectorized: float4 loads, 16B (half2 x2) stores
__global__ void ln_kernel(const float* __restrict__ in,
                          const float* __restrict__ gam,
                          const float* __restrict__ bet,
                          __half* __restrict__ out)
{
    int gwarp = (blockIdx.x * blockDim.x + threadIdx.x) >> 5;
    int lane  = threadIdx.x & 31;
    if (gwarp >= T_TOK) return;
    const float4* row = (const float4*)(in + (size_t)gwarp * H_DIM);
    float4 v[6];
    float s = 0.f, sq = 0.f;
#pragma unroll
    for (int i = 0; i < 6; i++) {
        v[i] = row[lane + 32 * i];
        s  += v[i].x + v[i].y + v[i].z + v[i].w;
        sq += v[i].x * v[i].x + v[i].y * v[i].y + v[i].z * v[i].z + v[i].w * v[i].w;
    }
#pragma unroll
    for (int o = 16; o > 0; o >>= 1) {
        s  += __shfl_xor_sync(0xffffffffu, s,  o);
        sq += __shfl_xor_sync(0xffffffffu, sq, o);
    }
    float mu  = s * (1.0f / H_DIM);
    float var = fmaxf(sq * (1.0f / H_DIM) - mu * mu, 0.0f);
    float rs  = rsqrtf(var + LN_EPS);
    __half* orow = out + (size_t)gwarp * H_DIM;
#pragma unroll
    for (int i = 0; i < 6; i++) {
        int j4 = lane + 32 * i;
        float4 g = *(const float4*)(gam + j4 * 4);
        float4 b = *(const float4*)(bet + j4 * 4);
        float o0 = (v[i].x - mu) * rs * g.x + b.x;
        float o1 = (v[i].y - mu) * rs * g.y + b.y;
        float o2 = (v[i].z - mu) * rs * g.z + b.z;
        float o3 = (v[i].w - mu) * rs * g.w + b.w;
        uint2 pk;
        ((__half2*)&pk.x)[0] = __floats2half2_rn(o0, o1);
        ((__half2*)&pk.y)[0] = __floats2half2_rn(o2, o3);
        *(uint2*)(orow + j4 * 4) = pk;
    }
}

// ------------------------------------------------- criss-cross attention core
// half2-vectorized: each thread handles 2 adjacent kf
__global__ void attn_kernel(const __half* __restrict__ qkv, __half* __restrict__ ctx)
{
    int gid = blockIdx.x * blockDim.x + threadIdx.x; // t*128 + p
    int t  = gid >> 7;
    int p  = (gid & 127) * 2;
    const __half* base = qkv + (size_t)t * (3 * H_DIM);
    float2 q[3], k[3], v[3];
#pragma unroll
    for (int c = 0; c < 3; c++) {
        q[c] = __half22float2(*(const __half2*)(base + c * H_DIM + p));
        k[c] = __half22float2(*(const __half2*)(base + c * H_DIM + KFD + p));
        v[c] = __half22float2(*(const __half2*)(base + c * H_DIM + 2 * KFD + p));
    }
    const float scale = 0.0625f;
    float o0x = 0.f, o1x = 0.f, o2x = 0.f;
    float o0y = 0.f, o1y = 0.f, o2y = 0.f;
#pragma unroll
    for (int c = 0; c < 3; c++) {
        {
            float s0 = q[c].x * k[0].x * scale;
            float s1 = q[c].x * k[1].x * scale;
            float s2 = q[c].x * k[2].x * scale;
            float m  = fmaxf(s0, fmaxf(s1, s2));
            float e0 = __expf(s0 - m), e1 = __expf(s1 - m), e2 = __expf(s2 - m);
            float inv = v[c].x / (e0 + e1 + e2);
            o0x = fmaf(e0, inv, o0x);
            o1x = fmaf(e1, inv, o1x);
            o2x = fmaf(e2, inv, o2x);
        }
        {
            float s0 = q[c].y * k[0].y * scale;
            float s1 = q[c].y * k[1].y * scale;
            float s2 = q[c].y * k[2].y * scale;
            float m  = fmaxf(s0, fmaxf(s1, s2));
            float e0 = __expf(s0 - m), e1 = __expf(s1 - m), e2 = __expf(s2 - m);
            float inv = v[c].y / (e0 + e1 + e2);
            o0y = fmaf(e0, inv, o0y);
            o1y = fmaf(e1, inv, o1y);
            o2y = fmaf(e2, inv, o2y);
        }
    }
    __half* ob = ctx + (size_t)t * 3 * KFD + p;
    *(__half2*)(ob)           = __floats2half2_rn(o0x, o0y);
    *(__half2*)(ob + KFD)     = __floats2half2_rn(o1x, o1y);
    *(__half2*)(ob + 2 * KFD) = __floats2half2_rn(o2x, o2y);
}

// ---------------------------------------------------------------- FP16 GEMM
// C[M,N] = A[M,K] @ BT[N,K]^T (+bias / +bias+res / gelu(+bias))
// CTA 128x128, 128 threads (4 warps, 2x2 of 64x64), 3-stage cp.async,
// 96KB smem -> 2 CTAs/SM. SW128-swizzled rows, ldmatrix, frag double-buffer.
// Half outputs (EPI 0/2) staged through smem for 16B coalesced stores.
template <int EPI, typename TO>
__global__ void __launch_bounds__(128, 2)
hgemm_kernel(int K,
             const __half* __restrict__ A, int lda, size_t az,
             const __half* __restrict__ BT, int ldb, size_t bz,
             TO* __restrict__ C, int ldc, size_t cz,
             const float* __restrict__ bias, size_t biasz,
             const float* __restrict__ res)
{
    extern __shared__ char smem[];
    const uint32_t sbase = (uint32_t)__cvta_generic_to_shared(smem);

    const int tid  = threadIdx.x;
    const int wid  = tid >> 5;
    const int lane = tid & 31;
    const int gID  = lane >> 2;
    const int tig  = lane & 3;
    const int wm   = (wid >> 1) * 64;
    const int wn   = (wid & 1) * 64;
    const int row0 = blockIdx.y * GBM;
    const int col0 = blockIdx.x * GBN;

    A    += (size_t)blockIdx.z * az;
    BT   += (size_t)blockIdx.z * bz;
    C    += (size_t)blockIdx.z * cz;
    bias += (size_t)blockIdx.z * biasz;

    const __half* Ag = A + (size_t)row0 * lda;
    const __half* Bg = BT + (size_t)col0 * ldb;

    // copy mapping: 128 threads, A: 8 chunks/thread, B: 8 chunks/thread
    const int cr = tid >> 3;          // 0..15
    const int cc = tid & 7;           // logical 16B chunk

    // ldmatrix lane geometry
    const int lrA = wm + (lane & 15);
    const int lrB = wn + (lane & 15);
    const int hi  = lane >> 4;
    const int sxA = lrA & 7;
    const int sxB = lrB & 7;

    float acc[4][8][4];
#pragma unroll
    for (int mi = 0; mi < 4; mi++)
#pragma unroll
        for (int ni = 0; ni < 8; ni++)
#pragma unroll
            for (int j = 0; j < 4; j++) acc[mi][ni][j] = 0.f;

    const int nk = K / BKH;

    // prologue
#pragma unroll
    for (int s = 0; s < STAGES - 1; s++) {
        if (s < nk) {
            uint32_t as = sbase + s * STAGE_BYTES;
            uint32_t bs = as + A_BYTES;
            int k0 = s * BKH;
#pragma unroll
            for (int i = 0; i < 8; i++) {
                int r = cr + 16 * i, c = cc;
                cp16(as + r * 128 + ((c ^ (r & 7)) << 4),
                     Ag + (size_t)r * lda + k0 + c * 8);
                cp16(bs + r * 128 + ((c ^ (r & 7)) << 4),
                     Bg + (size_t)r * ldb + k0 + c * 8);
            }
        }
        asm volatile("cp.async.commit_group;\n");
    }

    for (int kt = 0; kt < nk; kt++) {
        asm volatile("cp.async.wait_group %0;\n" :: "n"(STAGES - 2));
        __syncthreads();

        // issue stage kt+STAGES-1
        {
            int kf = kt + STAGES - 1;
            if (kf < nk) {
                uint32_t as = sbase + (kf % STAGES) * STAGE_BYTES;
                uint32_t bs = as + A_BYTES;
                int k0 = kf * BKH;
#pragma unroll
                for (int i = 0; i < 8; i++) {
                    int r = cr + 16 * i, c = cc;
                    cp16(as + r * 128 + ((c ^ (r & 7)) << 4),
                         Ag + (size_t)r * lda + k0 + c * 8);
                    cp16(bs + r * 128 + ((c ^ (r & 7)) << 4),
                         Bg + (size_t)r * ldb + k0 + c * 8);
                }
            }
            asm volatile("cp.async.commit_group;\n");
        }

        const uint32_t abase = sbase + (kt % STAGES) * STAGE_BYTES + lrA * 128;
        const uint32_t bbase = sbase + (kt % STAGES) * STAGE_BYTES + A_BYTES + lrB * 128;

        uint32_t af[2][4][4], bf[2][4][4];
        {
            uint32_t chA = (uint32_t)((hi ^ sxA) << 4);
            uint32_t chB = (uint32_t)((hi ^ sxB) << 4);
#pragma unroll
            for (int mi = 0; mi < 4; mi++) ldsm4(af[0][mi], abase + mi * 2048 + chA);
#pragma unroll
            for (int p = 0; p < 4; p++) ldsm4(bf[0][p], bbase + p * 2048 + chB);
        }
#pragma unroll
        for (int s = 0; s < 4; s++) {
            int cur = s & 1, nxt = cur ^ 1;
            if (s < 3) {
                uint32_t chA = (uint32_t)(((2 * (s + 1) + hi) ^ sxA) << 4);
                uint32_t chB = (uint32_t)(((2 * (s + 1) + hi) ^ sxB) << 4);
#pragma unroll
                for (int mi = 0; mi < 4; mi++) ldsm4(af[nxt][mi], abase + mi * 2048 + chA);
#pragma unroll
                for (int p = 0; p < 4; p++) ldsm4(bf[nxt][p], bbase + p * 2048 + chB);
            }
#pragma unroll
            for (int mi = 0; mi < 4; mi++)
#pragma unroll
                for (int p = 0; p < 4; p++) {
                    mma_f16(acc[mi][2 * p],     af[cur][mi], bf[cur][p][0], bf[cur][p][2]);
                    mma_f16(acc[mi][2 * p + 1], af[cur][mi], bf[cur][p][1], bf[cur][p][3]);
                }
        }
        __syncthreads();
    }

    if (EPI == 1) {
        // fp32 out + residual: direct float2 stores (full 32B sectors)
#pragma unroll
        for (int mi = 0; mi < 4; mi++) {
#pragma unroll
            for (int ni = 0; ni < 8; ni++) {
                int c = col0 + wn + ni * 8 + tig * 2;
                float2 bv = *(const float2*)(bias + c);
#pragma unroll
                for (int h = 0; h < 2; h++) {
                    int r = row0 + wm + mi * 16 + gID + h * 8;
                    float v0 = acc[mi][ni][h * 2 + 0] + bv.x;
                    float v1 = acc[mi][ni][h * 2 + 1] + bv.y;
                    float2 rv = *(const float2*)(res + (size_t)r * ldc + c);
                    v0 += rv.x;
                    v1 += rv.y;
                    *(float2*)((float*)C + (size_t)r * ldc + c) = make_float2(v0, v1);
                }
            }
        }
    } else {
        // half out: stage warp's 64x64 tile in private 8KB smem (swizzled),
        // then 16B coalesced stores. Mainloop's final __syncthreads makes the
        // stage buffers safe to reuse; each warp touches only its own region.
        char* wsm = smem + wid * 8192;
#pragma unroll
        for (int mi = 0; mi < 4; mi++) {
#pragma unroll
            for (int ni = 0; ni < 8; ni++) {
                float2 bv = *(const float2*)(bias + col0 + wn + ni * 8 + tig * 2);
#pragma unroll
                for (int h = 0; h < 2; h++) {
                    int r = mi * 16 + gID + h * 8;
                    float v0 = acc[mi][ni][h * 2 + 0] + bv.x;
                    float v1 = acc[mi][ni][h * 2 + 1] + bv.y;
                    if (EPI == 2) {
                        v0 = gelu_exact(v0);
                        v1 = gelu_exact(v1);
                    }
                    *(__half2*)(wsm + r * 128 + ((ni ^ (r & 7)) << 4) + tig * 4) =
                        __floats2half2_rn(v0, v1);
                }
            }
        }
        __syncwarp();
#pragma unroll
        for (int it = 0; it < 16; it++) {
            int r = it * 4 + (lane >> 3);
            int c = lane & 7;
            uint4 val = *(uint4*)(wsm + r * 128 + ((c ^ (r & 7)) << 4));
            *(uint4*)((__half*)C + (size_t)(row0 + wm + r) * ldc + col0 + wn + c * 8) = val;
        }
    }
}

// ---------------------------------------------------------------- launch
extern "C" void kernel_launch(void* const* d_in, const int* in_sizes, int n_in,
                              void* d_out, int out_size)
{
    const float* x     = (const float*)d_in[0];
    const float* W_qkv = (const float*)d_in[1];
    const float* b_qkv = (const float*)d_in[2];
    const float* W_out = (const float*)d_in[3];
    const float* b_out = (const float*)d_in[4];
    const float* ln1_g = (const float*)d_in[5];
    const float* ln1_b = (const float*)d_in[6];
    const float* ln2_g = (const float*)d_in[7];
    const float* ln2_b = (const float*)d_in[8];
    const float* W1    = (const float*)d_in[9];
    const float* b1    = (const float*)d_in[10];
    const float* W2    = (const float*)d_in[11];
    const float* b2    = (const float*)d_in[12];
    float* out = (float*)d_out;

    __half *s1, *s2, *w;
    float *xr;
    cudaGetSymbolAddress((void**)&s1, g_s1);
    cudaGetSymbolAddress((void**)&s2, g_s2);
    cudaGetSymbolAddress((void**)&xr, g_xr);
    cudaGetSymbolAddress((void**)&w,  g_w);

    cudaFuncSetAttribute((const void*)hgemm_kernel<0, __half>,
                         cudaFuncAttributeMaxDynamicSharedMemorySize, SMEMG_BYTES);
    cudaFuncSetAttribute((const void*)hgemm_kernel<1, float>,
                         cudaFuncAttributeMaxDynamicSharedMemorySize, SMEMG_BYTES);
    cudaFuncSetAttribute((const void*)hgemm_kernel<2, __half>,
                         cudaFuncAttributeMaxDynamicSharedMemorySize, SMEMG_BYTES);

    // 0) transpose + fp16-round all weights: W[K,N] -> WT[N,K]
    transpose_h_kernel<<<dim3(768 / 32, 256 / 32, 3), dim3(32, 8)>>>(W_qkv, w + WOFF_QKV, 256, 768);
    transpose_h_kernel<<<dim3(256 / 32, 256 / 32, 1), dim3(32, 8)>>>(W_out, w + WOFF_OUT, 256, 256);
    transpose_h_kernel<<<dim3(3072 / 32, 768 / 32, 1), dim3(32, 8)>>>(W1, w + WOFF_W1, 768, 3072);
    transpose_h_kernel<<<dim3(768 / 32, 3072 / 32, 1), dim3(32, 8)>>>(W2, w + WOFF_W2, 3072, 768);

    // 1) LN1: x -> h (s2, half)
    ln_kernel<<<T_TOK / 8, 256>>>(x, ln1_g, ln1_b, s2);

    // 2) QKV (all 3 channels, gridDim.z=3): [32768,256] @ [256,768] -> s1[T,2304]
    hgemm_kernel<0, __half><<<dim3(6, 256, 3), 128, SMEMG_BYTES>>>(
        KFD,
        s2, H_DIM, (size_t)KFD,
        w + WOFF_QKV, KFD, (size_t)768 * 256,
        s1, 2304, (size_t)768,
        b_qkv, (size_t)768,
        nullptr);

    // 3) attention: qkv(s1) -> ctx(s2) [T*3, 256] half
    attn_kernel<<<(T_TOK * 128) / 256, 256>>>(s1, s2);

    // 4) out-proj + residual: [98304,256] @ [256,256] + x -> xr (fp32)
    hgemm_kernel<1, float><<<dim3(2, 768, 1), 128, SMEMG_BYTES>>>(
        KFD, s2, KFD, 0, w + WOFF_OUT, KFD, 0, xr, KFD, 0, b_out, 0, x);

    // 5) LN2: xr -> y (s2, half)
    ln_kernel<<<T_TOK / 8, 256>>>(xr, ln2_g, ln2_b, s2);

    // 6) MLP fc1 + GELU: [32768,768] @ [768,3072] -> act (s1, half)
    hgemm_kernel<2, __half><<<dim3(24, 256, 1), 128, SMEMG_BYTES>>>(
        H_DIM, s2, H_DIM, 0, w + WOFF_W1, H_DIM, 0, s1, M_MLP, 0, b1, 0, nullptr);

    // 7) MLP fc2 + residual: [32768,3072] @ [3072,768] + xr -> out (fp32)
    hgemm_kernel<1, float><<<dim3(6, 256, 1), 128, SMEMG_BYTES>>>(
        M_MLP, s1, M_MLP, 0, w + WOFF_W2, M_MLP, 0, out, H_DIM, 0, b2, 0, xr);
}

// round 12
// speedup vs baseline: 1.4727x; 1.4727x over previous
#include <cuda_runtime.h>
#include <cuda_fp16.h>
#include <math.h>
#include <stdint.h>

#define T_TOK 32768
#define H_DIM 768
#define C_CH  3
#define KFD   256
#define M_MLP 3072
#define LN_EPS 1e-6f

// ---- GEMM tiling (fp16 mma.sync m16n8k16, swizzled smem, ldmatrix) ----
#define GBM 128
#define GBN 128
#define BKH 64                     // halves per K-tile (128B rows)
#define STAGES 3
#define A_BYTES (GBM * 128)        // 16384
#define B_BYTES (GBN * 128)        // 16384
#define STAGE_BYTES (A_BYTES + B_BYTES)     // 32768
#define SMEMG_BYTES (STAGES * STAGE_BYTES)  // 98304

// Scratch (device globals; no allocations anywhere).
__device__ __align__(16) __half g_s1[(size_t)T_TOK * M_MLP];  // qkv [T,2304] then act [T,3072]
__device__ __align__(16) __half g_s2[(size_t)T_TOK * H_DIM];  // h / ctx / y
__device__ __align__(16) float  g_xr[(size_t)T_TOK * H_DIM];
// transposed fp16 weights (K-major rows [N,K]):
#define WOFF_QKV 0
#define WOFF_OUT 589824
#define WOFF_W1  655360
#define WOFF_W2  3014656
__device__ __align__(16) __half g_w[5373952];

// ---------------------------------------------------------------- helpers
__device__ __forceinline__ float gelu_exact(float x)
{
    return 0.5f * x * (1.0f + erff(x * 0.70710678118654752f));
}

__device__ __forceinline__ void cp16(uint32_t dst_smem, const void* src)
{
    asm volatile("cp.async.cg.shared.global [%0], [%1], 16;\n" :: "r"(dst_smem), "l"(src));
}

__device__ __forceinline__ void ldsm4(uint32_t* r, uint32_t addr)
{
    asm volatile("ldmatrix.sync.aligned.m8n8.x4.shared.b16 {%0,%1,%2,%3}, [%4];"
                 : "=r"(r[0]), "=r"(r[1]), "=r"(r[2]), "=r"(r[3]) : "r"(addr));
}

__device__ __forceinline__ void mma_f16(float* d, const uint32_t* a,
                                        uint32_t b0, uint32_t b1)
{
    asm volatile(
        "mma.sync.aligned.m16n8k16.row.col.f32.f16.f16.f32 "
        "{%0,%1,%2,%3}, {%4,%5,%6,%7}, {%8,%9}, {%0,%1,%2,%3};\n"
        : "+f"(d[0]), "+f"(d[1]), "+f"(d[2]), "+f"(d[3])
        : "r"(a[0]), "r"(a[1]), "r"(a[2]), "r"(a[3]), "r"(b0), "r"(b1));
}

// ---------------------------------------------------------------- transpose+half
__global__ void transpose_h_kernel(const float* __restrict__ in,
                                   __half* __restrict__ out, int K, int N)
{
    __shared__ float t[32][33];
    size_t bo = (size_t)blockIdx.z * K * N;
    in += bo;
    out += bo;
    int k0 = blockIdx.y * 32, n0 = blockIdx.x * 32;
    int x = threadIdx.x, y = threadIdx.y;
#pragma unroll
    for (int i = 0; i < 32; i += 8)
        t[y + i][x] = in[(size_t)(k0 + y + i) * N + n0 + x];
    __syncthreads();
#pragma unroll
    for (int i = 0; i < 32; i += 8)
        out[(size_t)(n0 + y + i) * K + k0 + x] = __float2half_rn(t[x][y + i]);
}

// ---------------------------------------------------------------- LayerNorm -> half
// vectorized: float4 loads, 16B (half2 x2) stores
__global__ void ln_kernel(const float* __restrict__ in,
                          const float* __restrict__ gam,
                          const float* __restrict__ bet,
                          __half* __restrict__ out)
{
    int gwarp = (blockIdx.x * blockDim.x + threadIdx.x) >> 5;
    int lane  = threadIdx.x & 31;
    if (gwarp >= T_TOK) return;
    const float4* row = (const float4*)(in + (size_t)gwarp * H_DIM);
    float4 v[6];
    float s = 0.f, sq = 0.f;
#pragma unroll
    for (int i = 0; i < 6; i++) {
        v[i] = row[lane + 32 * i];
        s  += v[i].x + v[i].y + v[i].z + v[i].w;
        sq += v[i].x * v[i].x + v[i].y * v[i].y + v[i].z * v[i].z + v[i].w * v[i].w;
    }
#pragma unroll
    for (int o = 16; o > 0; o >>= 1) {
        s  += __shfl_xor_sync(0xffffffffu, s,  o);
        sq += __shfl_xor_sync(0xffffffffu, sq, o);
    }
    float mu  = s * (1.0f / H_DIM);
    float var = fmaxf(sq * (1.0f / H_DIM) - mu * mu, 0.0f);
    float rs  = rsqrtf(var + LN_EPS);
    __half* orow = out + (size_t)gwarp * H_DIM;
#pragma unroll
    for (int i = 0; i < 6; i++) {
        int j4 = lane + 32 * i;
        float4 g = *(const float4*)(gam + j4 * 4);
        float4 b = *(const float4*)(bet + j4 * 4);
        float o0 = (v[i].x - mu) * rs * g.x + b.x;
        float o1 = (v[i].y - mu) * rs * g.y + b.y;
        float o2 = (v[i].z - mu) * rs * g.z + b.z;
        float o3 = (v[i].w - mu) * rs * g.w + b.w;
        uint2 pk;
        ((__half2*)&pk.x)[0] = __floats2half2_rn(o0, o1);
        ((__half2*)&pk.y)[0] = __floats2half2_rn(o2, o3);
        *(uint2*)(orow + j4 * 4) = pk;
    }
}

// ------------------------------------------------- criss-cross attention core
// half2-vectorized: each thread handles 2 adjacent kf
__global__ void attn_kernel(const __half* __restrict__ qkv, __half* __restrict__ ctx)
{
    int gid = blockIdx.x * blockDim.x + threadIdx.x; // t*128 + p
    int t  = gid >> 7;
    int p  = (gid & 127) * 2;
    const __half* base = qkv + (size_t)t * (3 * H_DIM);
    float2 q[3], k[3], v[3];
#pragma unroll
    for (int c = 0; c < 3; c++) {
        q[c] = __half22float2(*(const __half2*)(base + c * H_DIM + p));
        k[c] = __half22float2(*(const __half2*)(base + c * H_DIM + KFD + p));
        v[c] = __half22float2(*(const __half2*)(base + c * H_DIM + 2 * KFD + p));
    }
    const float scale = 0.0625f;
    float o0x = 0.f, o1x = 0.f, o2x = 0.f;
    float o0y = 0.f, o1y = 0.f, o2y = 0.f;
#pragma unroll
    for (int c = 0; c < 3; c++) {
        {
            float s0 = q[c].x * k[0].x * scale;
            float s1 = q[c].x * k[1].x * scale;
            float s2 = q[c].x * k[2].x * scale;
            float m  = fmaxf(s0, fmaxf(s1, s2));
            float e0 = __expf(s0 - m), e1 = __expf(s1 - m), e2 = __expf(s2 - m);
            float inv = v[c].x / (e0 + e1 + e2);
            o0x = fmaf(e0, inv, o0x);
            o1x = fmaf(e1, inv, o1x);
            o2x = fmaf(e2, inv, o2x);
        }
        {
            float s0 = q[c].y * k[0].y * scale;
            float s1 = q[c].y * k[1].y * scale;
            float s2 = q[c].y * k[2].y * scale;
            float m  = fmaxf(s0, fmaxf(s1, s2));
            float e0 = __expf(s0 - m), e1 = __expf(s1 - m), e2 = __expf(s2 - m);
            float inv = v[c].y / (e0 + e1 + e2);
            o0y = fmaf(e0, inv, o0y);
            o1y = fmaf(e1, inv, o1y);
            o2y = fmaf(e2, inv, o2y);
        }
    }
    __half* ob = ctx + (size_t)t * 3 * KFD + p;
    *(__half2*)(ob)           = __floats2half2_rn(o0x, o0y);
    *(__half2*)(ob + KFD)     = __floats2half2_rn(o1x, o1y);
    *(__half2*)(ob + 2 * KFD) = __floats2half2_rn(o2x, o2y);
}

// ---------------------------------------------------------------- FP16 GEMM
// C[M,N] = A[M,K] @ BT[N,K]^T (+bias / +bias+res / gelu(+bias))
// CTA 128x128, 128 threads (4 warps, 2x2 of 64x64), 3-stage cp.async,
// 96KB smem -> 2 CTAs/SM. SW128-swizzled rows, ldmatrix, frag double-buffer.
// Register-lean direct epilogue (no smem staging; see R11 spill post-mortem).
template <int EPI, typename TO>
__global__ void __launch_bounds__(128, 2)
hgemm_kernel(int K,
             const __half* __restrict__ A, int lda, size_t az,
             const __half* __restrict__ BT, int ldb, size_t bz,
             TO* __restrict__ C, int ldc, size_t cz,
             const float* __restrict__ bias, size_t biasz,
             const float* __restrict__ res)
{
    extern __shared__ char smem[];
    const uint32_t sbase = (uint32_t)__cvta_generic_to_shared(smem);

    const int tid  = threadIdx.x;
    const int wid  = tid >> 5;
    const int lane = tid & 31;
    const int gID  = lane >> 2;
    const int tig  = lane & 3;
    const int wm   = (wid >> 1) * 64;
    const int wn   = (wid & 1) * 64;
    const int row0 = blockIdx.y * GBM;
    const int col0 = blockIdx.x * GBN;

    A    += (size_t)blockIdx.z * az;
    BT   += (size_t)blockIdx.z * bz;
    C    += (size_t)blockIdx.z * cz;
    bias += (size_t)blockIdx.z * biasz;

    const __half* Ag = A + (size_t)row0 * lda;
    const __half* Bg = BT + (size_t)col0 * ldb;

    // copy mapping: 128 threads, A: 8 chunks/thread, B: 8 chunks/thread
    const int cr = tid >> 3;          // 0..15
    const int cc = tid & 7;           // logical 16B chunk

    // ldmatrix lane geometry
    const int lrA = wm + (lane & 15);
    const int lrB = wn + (lane & 15);
    const int hi  = lane >> 4;
    const int sxA = lrA & 7;
    const int sxB = lrB & 7;

    float acc[4][8][4];
#pragma unroll
    for (int mi = 0; mi < 4; mi++)
#pragma unroll
        for (int ni = 0; ni < 8; ni++)
#pragma unroll
            for (int j = 0; j < 4; j++) acc[mi][ni][j] = 0.f;

    const int nk = K / BKH;

    // prologue
#pragma unroll
    for (int s = 0; s < STAGES - 1; s++) {
        if (s < nk) {
            uint32_t as = sbase + s * STAGE_BYTES;
            uint32_t bs = as + A_BYTES;
            int k0 = s * BKH;
#pragma unroll
            for (int i = 0; i < 8; i++) {
                int r = cr + 16 * i, c = cc;
                cp16(as + r * 128 + ((c ^ (r & 7)) << 4),
                     Ag + (size_t)r * lda + k0 + c * 8);
                cp16(bs + r * 128 + ((c ^ (r & 7)) << 4),
                     Bg + (size_t)r * ldb + k0 + c * 8);
            }
        }
        asm volatile("cp.async.commit_group;\n");
    }

    for (int kt = 0; kt < nk; kt++) {
        asm volatile("cp.async.wait_group %0;\n" :: "n"(STAGES - 2));
        __syncthreads();

        // issue stage kt+STAGES-1
        {
            int kf = kt + STAGES - 1;
            if (kf < nk) {
                uint32_t as = sbase + (kf % STAGES) * STAGE_BYTES;
                uint32_t bs = as + A_BYTES;
                int k0 = kf * BKH;
#pragma unroll
                for (int i = 0; i < 8; i++) {
                    int r = cr + 16 * i, c = cc;
                    cp16(as + r * 128 + ((c ^ (r & 7)) << 4),
                         Ag + (size_t)r * lda + k0 + c * 8);
                    cp16(bs + r * 128 + ((c ^ (r & 7)) << 4),
                         Bg + (size_t)r * ldb + k0 + c * 8);
                }
            }
            asm volatile("cp.async.commit_group;\n");
        }

        const uint32_t abase = sbase + (kt % STAGES) * STAGE_BYTES + lrA * 128;
        const uint32_t bbase = sbase + (kt % STAGES) * STAGE_BYTES + A_BYTES + lrB * 128;

        uint32_t af[2][4][4], bf[2][4][4];
        {
            uint32_t chA = (uint32_t)((hi ^ sxA) << 4);
            uint32_t chB = (uint32_t)((hi ^ sxB) << 4);
#pragma unroll
            for (int mi = 0; mi < 4; mi++) ldsm4(af[0][mi], abase + mi * 2048 + chA);
#pragma unroll
            for (int p = 0; p < 4; p++) ldsm4(bf[0][p], bbase + p * 2048 + chB);
        }
#pragma unroll
        for (int s = 0; s < 4; s++) {
            int cur = s & 1, nxt = cur ^ 1;
            if (s < 3) {
                uint32_t chA = (uint32_t)(((2 * (s + 1) + hi) ^ sxA) << 4);
                uint32_t chB = (uint32_t)(((2 * (s + 1) + hi) ^ sxB) << 4);
#pragma unroll
                for (int mi = 0; mi < 4; mi++) ldsm4(af[nxt][mi], abase + mi * 2048 + chA);
#pragma unroll
                for (int p = 0; p < 4; p++) ldsm4(bf[nxt][p], bbase + p * 2048 + chB);
            }
#pragma unroll
            for (int mi = 0; mi < 4; mi++)
#pragma unroll
                for (int p = 0; p < 4; p++) {
                    mma_f16(acc[mi][2 * p],     af[cur][mi], bf[cur][p][0], bf[cur][p][2]);
                    mma_f16(acc[mi][2 * p + 1], af[cur][mi], bf[cur][p][1], bf[cur][p][3]);
                }
        }
        __syncthreads();
    }

    // epilogue (register-lean, direct stores)
#pragma unroll
    for (int mi = 0; mi < 4; mi++) {
#pragma unroll
        for (int ni = 0; ni < 8; ni++) {
            int c = col0 + wn + ni * 8 + tig * 2;
            float2 bv = *(const float2*)(bias + c);
#pragma unroll
            for (int h = 0; h < 2; h++) {
                int r = row0 + wm + mi * 16 + gID + h * 8;
                float v0 = acc[mi][ni][h * 2 + 0] + bv.x;
                float v1 = acc[mi][ni][h * 2 + 1] + bv.y;
                if (EPI == 1) {
                    float2 rv = *(const float2*)(res + (size_t)r * ldc + c);
                    v0 += rv.x;
                    v1 += rv.y;
                    *(float2*)((float*)C + (size_t)r * ldc + c) = make_float2(v0, v1);
                } else if (EPI == 2) {
                    __half2 o = __floats2half2_rn(gelu_exact(v0), gelu_exact(v1));
                    *(__half2*)((__half*)C + (size_t)r * ldc + c) = o;
                } else {
                    __half2 o = __floats2half2_rn(v0, v1);
                    *(__half2*)((__half*)C + (size_t)r * ldc + c) = o;
                }
            }
        }
    }
}

// ---------------------------------------------------------------- launch
extern "C" void kernel_launch(void* const* d_in, const int* in_sizes, int n_in,
                              void* d_out, int out_size)
{
    const float* x     = (const float*)d_in[0];
    const float* W_qkv = (const float*)d_in[1];
    const float* b_qkv = (const float*)d_in[2];
    const float* W_out = (const float*)d_in[3];
    const float* b_out = (const float*)d_in[4];
    const float* ln1_g = (const float*)d_in[5];
    const float* ln1_b = (const float*)d_in[6];
    const float* ln2_g = (const float*)d_in[7];
    const float* ln2_b = (const float*)d_in[8];
    const float* W1    = (const float*)d_in[9];
    const float* b1    = (const float*)d_in[10];
    const float* W2    = (const float*)d_in[11];
    const float* b2    = (const float*)d_in[12];
    float* out = (float*)d_out;

    __half *s1, *s2, *w;
    float *xr;
    cudaGetSymbolAddress((void**)&s1, g_s1);
    cudaGetSymbolAddress((void**)&s2, g_s2);
    cudaGetSymbolAddress((void**)&xr, g_xr);
    cudaGetSymbolAddress((void**)&w,  g_w);

    cudaFuncSetAttribute((const void*)hgemm_kernel<0, __half>,
                         cudaFuncAttributeMaxDynamicSharedMemorySize, SMEMG_BYTES);
    cudaFuncSetAttribute((const void*)hgemm_kernel<1, float>,
                         cudaFuncAttributeMaxDynamicSharedMemorySize, SMEMG_BYTES);
    cudaFuncSetAttribute((const void*)hgemm_kernel<2, __half>,
                         cudaFuncAttributeMaxDynamicSharedMemorySize, SMEMG_BYTES);

    // 0) transpose + fp16-round all weights: W[K,N] -> WT[N,K]
    transpose_h_kernel<<<dim3(768 / 32, 256 / 32, 3), dim3(32, 8)>>>(W_qkv, w + WOFF_QKV, 256, 768);
    transpose_h_kernel<<<dim3(256 / 32, 256 / 32, 1), dim3(32, 8)>>>(W_out, w + WOFF_OUT, 256, 256);
    transpose_h_kernel<<<dim3(3072 / 32, 768 / 32, 1), dim3(32, 8)>>>(W1, w + WOFF_W1, 768, 3072);
    transpose_h_kernel<<<dim3(768 / 32, 3072 / 32, 1), dim3(32, 8)>>>(W2, w + WOFF_W2, 3072, 768);

    // 1) LN1: x -> h (s2, half)
    ln_kernel<<<T_TOK / 8, 256>>>(x, ln1_g, ln1_b, s2);

    // 2) QKV (all 3 channels, gridDim.z=3): [32768,256] @ [256,768] -> s1[T,2304]
    hgemm_kernel<0, __half><<<dim3(6, 256, 3), 128, SMEMG_BYTES>>>(
        KFD,
        s2, H_DIM, (size_t)KFD,
        w + WOFF_QKV, KFD, (size_t)768 * 256,
        s1, 2304, (size_t)768,
        b_qkv, (size_t)768,
        nullptr);

    // 3) attention: qkv(s1) -> ctx(s2) [T*3, 256] half
    attn_kernel<<<(T_TOK * 128) / 256, 256>>>(s1, s2);

    // 4) out-proj + residual: [98304,256] @ [256,256] + x -> xr (fp32)
    hgemm_kernel<1, float><<<dim3(2, 768, 1), 128, SMEMG_BYTES>>>(
        KFD, s2, KFD, 0, w + WOFF_OUT, KFD, 0, xr, KFD, 0, b_out, 0, x);

    // 5) LN2: xr -> y (s2, half)
    ln_kernel<<<T_TOK / 8, 256>>>(xr, ln2_g, ln2_b, s2);

    // 6) MLP fc1 + GELU: [32768,768] @ [768,3072] -> act (s1, half)
    hgemm_kernel<2, __half><<<dim3(24, 256, 1), 128, SMEMG_BYTES>>>(
        H_DIM, s2, H_DIM, 0, w + WOFF_W1, H_DIM, 0, s1, M_MLP, 0, b1, 0, nullptr);

    // 7) MLP fc2 + residual: [32768,3072] @ [3072,768] + xr -> out (fp32)
    hgemm_kernel<1, float><<<dim3(6, 256, 1), 128, SMEMG_BYTES>>>(
        M_MLP, s1, M_MLP, 0, w + WOFF_W2, M_MLP, 0, out, H_DIM, 0, b2, 0, xr);
}

// round 13
// speedup vs baseline: 1.5006x; 1.0189x over previous
#include <cuda_runtime.h>
#include <cuda_fp16.h>
#include <math.h>
#include <stdint.h>

#define T_TOK 32768
#define H_DIM 768
#define C_CH  3
#define KFD   256
#define M_MLP 3072
#define LN_EPS 1e-6f

// ---- GEMM tiling (fp16 mma.sync m16n8k16, swizzled smem, ldmatrix) ----
#define GBM 128
#define GBN 128
#define BKH 64                     // halves per K-tile (128B rows)
#define STAGES 3
#define A_BYTES (GBM * 128)        // 16384
#define B_BYTES (GBN * 128)        // 16384
#define STAGE_BYTES (A_BYTES + B_BYTES)     // 32768
#define SMEMG_BYTES (STAGES * STAGE_BYTES)  // 98304

// Scratch (device globals; no allocations anywhere).
__device__ __align__(16) __half g_s1[(size_t)T_TOK * M_MLP];  // qkv [T,2304] then act [T,3072]
__device__ __align__(16) __half g_s2[(size_t)T_TOK * H_DIM];  // h / ctx / y
__device__ __align__(16) float  g_xr[(size_t)T_TOK * H_DIM];
// transposed fp16 weights (K-major rows [N,K]):
#define WOFF_QKV 0
#define WOFF_OUT 589824
#define WOFF_W1  655360
#define WOFF_W2  3014656
__device__ __align__(16) __half g_w[5373952];

// ---------------------------------------------------------------- helpers
__device__ __forceinline__ float gelu_exact(float x)
{
    return 0.5f * x * (1.0f + erff(x * 0.70710678118654752f));
}

__device__ __forceinline__ void cp16(uint32_t dst_smem, const void* src)
{
    asm volatile("cp.async.cg.shared.global [%0], [%1], 16;\n" :: "r"(dst_smem), "l"(src));
}

__device__ __forceinline__ void ldsm4(uint32_t* r, uint32_t addr)
{
    asm volatile("ldmatrix.sync.aligned.m8n8.x4.shared.b16 {%0,%1,%2,%3}, [%4];"
                 : "=r"(r[0]), "=r"(r[1]), "=r"(r[2]), "=r"(r[3]) : "r"(addr));
}

__device__ __forceinline__ void mma_f16(float* d, const uint32_t* a,
                                        uint32_t b0, uint32_t b1)
{
    asm volatile(
        "mma.sync.aligned.m16n8k16.row.col.f32.f16.f16.f32 "
        "{%0,%1,%2,%3}, {%4,%5,%6,%7}, {%8,%9}, {%0,%1,%2,%3};\n"
        : "+f"(d[0]), "+f"(d[1]), "+f"(d[2]), "+f"(d[3])
        : "r"(a[0]), "r"(a[1]), "r"(a[2]), "r"(a[3]), "r"(b0), "r"(b1));
}

// ---------------------------------------------------------------- transpose+half
__global__ void transpose_h_kernel(const float* __restrict__ in,
                                   __half* __restrict__ out, int K, int N)
{
    __shared__ float t[32][33];
    size_t bo = (size_t)blockIdx.z * K * N;
    in += bo;
    out += bo;
    int k0 = blockIdx.y * 32, n0 = blockIdx.x * 32;
    int x = threadIdx.x, y = threadIdx.y;
#pragma unroll
    for (int i = 0; i < 32; i += 8)
        t[y + i][x] = in[(size_t)(k0 + y + i) * N + n0 + x];
    __syncthreads();
#pragma unroll
    for (int i = 0; i < 32; i += 8)
        out[(size_t)(n0 + y + i) * K + k0 + x] = __float2half_rn(t[x][y + i]);
}

// ---------------------------------------------------------------- LayerNorm -> half
// vectorized: float4 loads, 16B (half2 x2) stores
__global__ void ln_kernel(const float* __restrict__ in,
                          const float* __restrict__ gam,
                          const float* __restrict__ bet,
                          __half* __restrict__ out)
{
    int gwarp = (blockIdx.x * blockDim.x + threadIdx.x) >> 5;
    int lane  = threadIdx.x & 31;
    if (gwarp >= T_TOK) return;
    const float4* row = (const float4*)(in + (size_t)gwarp * H_DIM);
    float4 v[6];
    float s = 0.f, sq = 0.f;
#pragma unroll
    for (int i = 0; i < 6; i++) {
        v[i] = row[lane + 32 * i];
        s  += v[i].x + v[i].y + v[i].z + v[i].w;
        sq += v[i].x * v[i].x + v[i].y * v[i].y + v[i].z * v[i].z + v[i].w * v[i].w;
    }
#pragma unroll
    for (int o = 16; o > 0; o >>= 1) {
        s  += __shfl_xor_sync(0xffffffffu, s,  o);
        sq += __shfl_xor_sync(0xffffffffu, sq, o);
    }
    float mu  = s * (1.0f / H_DIM);
    float var = fmaxf(sq * (1.0f / H_DIM) - mu * mu, 0.0f);
    float rs  = rsqrtf(var + LN_EPS);
    __half* orow = out + (size_t)gwarp * H_DIM;
#pragma unroll
    for (int i = 0; i < 6; i++) {
        int j4 = lane + 32 * i;
        float4 g = *(const float4*)(gam + j4 * 4);
        float4 b = *(const float4*)(bet + j4 * 4);
        float o0 = (v[i].x - mu) * rs * g.x + b.x;
        float o1 = (v[i].y - mu) * rs * g.y + b.y;
        float o2 = (v[i].z - mu) * rs * g.z + b.z;
        float o3 = (v[i].w - mu) * rs * g.w + b.w;
        uint2 pk;
        ((__half2*)&pk.x)[0] = __floats2half2_rn(o0, o1);
        ((__half2*)&pk.y)[0] = __floats2half2_rn(o2, o3);
        *(uint2*)(orow + j4 * 4) = pk;
    }
}

// ------------------------------------------------- criss-cross attention core
// half2-vectorized: each thread handles 2 adjacent kf
__global__ void attn_kernel(const __half* __restrict__ qkv, __half* __restrict__ ctx)
{
    int gid = blockIdx.x * blockDim.x + threadIdx.x; // t*128 + p
    int t  = gid >> 7;
    int p  = (gid & 127) * 2;
    const __half* base = qkv + (size_t)t * (3 * H_DIM);
    float2 q[3], k[3], v[3];
#pragma unroll
    for (int c = 0; c < 3; c++) {
        q[c] = __half22float2(*(const __half2*)(base + c * H_DIM + p));
        k[c] = __half22float2(*(const __half2*)(base + c * H_DIM + KFD + p));
        v[c] = __half22float2(*(const __half2*)(base + c * H_DIM + 2 * KFD + p));
    }
    const float scale = 0.0625f;
    float o0x = 0.f, o1x = 0.f, o2x = 0.f;
    float o0y = 0.f, o1y = 0.f, o2y = 0.f;
#pragma unroll
    for (int c = 0; c < 3; c++) {
        {
            float s0 = q[c].x * k[0].x * scale;
            float s1 = q[c].x * k[1].x * scale;
            float s2 = q[c].x * k[2].x * scale;
            float m  = fmaxf(s0, fmaxf(s1, s2));
            float e0 = __expf(s0 - m), e1 = __expf(s1 - m), e2 = __expf(s2 - m);
            float inv = v[c].x / (e0 + e1 + e2);
            o0x = fmaf(e0, inv, o0x);
            o1x = fmaf(e1, inv, o1x);
            o2x = fmaf(e2, inv, o2x);
        }
        {
            float s0 = q[c].y * k[0].y * scale;
            float s1 = q[c].y * k[1].y * scale;
            float s2 = q[c].y * k[2].y * scale;
            float m  = fmaxf(s0, fmaxf(s1, s2));
            float e0 = __expf(s0 - m), e1 = __expf(s1 - m), e2 = __expf(s2 - m);
            float inv = v[c].y / (e0 + e1 + e2);
            o0y = fmaf(e0, inv, o0y);
            o1y = fmaf(e1, inv, o1y);
            o2y = fmaf(e2, inv, o2y);
        }
    }
    __half* ob = ctx + (size_t)t * 3 * KFD + p;
    *(__half2*)(ob)           = __floats2half2_rn(o0x, o0y);
    *(__half2*)(ob + KFD)     = __floats2half2_rn(o1x, o1y);
    *(__half2*)(ob + 2 * KFD) = __floats2half2_rn(o2x, o2y);
}

// ---------------------------------------------------------------- FP16 GEMM
// C[M,N] = A[M,K] @ BT[N,K]^T (+bias / +bias+res / gelu(+bias))
// CTA 128x128, 128 threads (4 warps, 2x2 of 64x64), 3-stage cp.async,
// 96KB smem -> 2 CTAs/SM. SW128-swizzled rows, ldmatrix, frag double-buffer.
// Single sync per K-tile; copies issued after step-0 MMAs (tensor-first order).
template <int EPI, typename TO>
__global__ void __launch_bounds__(128, 2)
hgemm_kernel(int K,
             const __half* __restrict__ A, int lda, size_t az,
             const __half* __restrict__ BT, int ldb, size_t bz,
             TO* __restrict__ C, int ldc, size_t cz,
             const float* __restrict__ bias, size_t biasz,
             const float* __restrict__ res)
{
    extern __shared__ char smem[];
    const uint32_t sbase = (uint32_t)__cvta_generic_to_shared(smem);

    const int tid  = threadIdx.x;
    const int wid  = tid >> 5;
    const int lane = tid & 31;
    const int gID  = lane >> 2;
    const int tig  = lane & 3;
    const int wm   = (wid >> 1) * 64;
    const int wn   = (wid & 1) * 64;
    const int row0 = blockIdx.y * GBM;
    const int col0 = blockIdx.x * GBN;

    A    += (size_t)blockIdx.z * az;
    BT   += (size_t)blockIdx.z * bz;
    C    += (size_t)blockIdx.z * cz;
    bias += (size_t)blockIdx.z * biasz;

    const __half* Ag = A + (size_t)row0 * lda;
    const __half* Bg = BT + (size_t)col0 * ldb;

    // copy mapping: 128 threads, A: 8 chunks/thread, B: 8 chunks/thread
    const int cr = tid >> 3;          // 0..15
    const int cc = tid & 7;           // logical 16B chunk

    // ldmatrix lane geometry
    const int lrA = wm + (lane & 15);
    const int lrB = wn + (lane & 15);
    const int hi  = lane >> 4;
    const int sxA = lrA & 7;
    const int sxB = lrB & 7;

    float acc[4][8][4];
#pragma unroll
    for (int mi = 0; mi < 4; mi++)
#pragma unroll
        for (int ni = 0; ni < 8; ni++)
#pragma unroll
            for (int j = 0; j < 4; j++) acc[mi][ni][j] = 0.f;

    const int nk = K / BKH;

    // prologue
#pragma unroll
    for (int s = 0; s < STAGES - 1; s++) {
        if (s < nk) {
            uint32_t as = sbase + s * STAGE_BYTES;
            uint32_t bs = as + A_BYTES;
            int k0 = s * BKH;
#pragma unroll
            for (int i = 0; i < 8; i++) {
                int r = cr + 16 * i, c = cc;
                cp16(as + r * 128 + ((c ^ (r & 7)) << 4),
                     Ag + (size_t)r * lda + k0 + c * 8);
                cp16(bs + r * 128 + ((c ^ (r & 7)) << 4),
                     Bg + (size_t)r * ldb + k0 + c * 8);
            }
        }
        asm volatile("cp.async.commit_group;\n");
    }

    for (int kt = 0; kt < nk; kt++) {
        asm volatile("cp.async.wait_group %0;\n" :: "n"(STAGES - 2));
        __syncthreads();

        const uint32_t abase = sbase + (kt % STAGES) * STAGE_BYTES + lrA * 128;
        const uint32_t bbase = sbase + (kt % STAGES) * STAGE_BYTES + A_BYTES + lrB * 128;

        uint32_t af[2][4][4], bf[2][4][4];
        // fragments for k-step 0 first: tensor work starts ASAP
        {
            uint32_t chA = (uint32_t)((hi ^ sxA) << 4);
            uint32_t chB = (uint32_t)((hi ^ sxB) << 4);
#pragma unroll
            for (int mi = 0; mi < 4; mi++) ldsm4(af[0][mi], abase + mi * 2048 + chA);
#pragma unroll
            for (int p = 0; p < 4; p++) ldsm4(bf[0][p], bbase + p * 2048 + chB);
        }
#pragma unroll
        for (int s = 0; s < 4; s++) {
            int cur = s & 1, nxt = cur ^ 1;
            if (s == 1) {
                // issue next-stage copies after step-0 MMAs are in flight
                int kf = kt + STAGES - 1;
                if (kf < nk) {
                    uint32_t as = sbase + (kf % STAGES) * STAGE_BYTES;
                    uint32_t bs = as + A_BYTES;
                    int k0 = kf * BKH;
#pragma unroll
                    for (int i = 0; i < 8; i++) {
                        int r = cr + 16 * i, c = cc;
                        cp16(as + r * 128 + ((c ^ (r & 7)) << 4),
                             Ag + (size_t)r * lda + k0 + c * 8);
                        cp16(bs + r * 128 + ((c ^ (r & 7)) << 4),
                             Bg + (size_t)r * ldb + k0 + c * 8);
                    }
                }
                asm volatile("cp.async.commit_group;\n");
            }
            if (s < 3) {
                uint32_t chA = (uint32_t)(((2 * (s + 1) + hi) ^ sxA) << 4);
                uint32_t chB = (uint32_t)(((2 * (s + 1) + hi) ^ sxB) << 4);
#pragma unroll
                for (int mi = 0; mi < 4; mi++) ldsm4(af[nxt][mi], abase + mi * 2048 + chA);
#pragma unroll
                for (int p = 0; p < 4; p++) ldsm4(bf[nxt][p], bbase + p * 2048 + chB);
            }
#pragma unroll
            for (int mi = 0; mi < 4; mi++)
#pragma unroll
                for (int p = 0; p < 4; p++) {
                    mma_f16(acc[mi][2 * p],     af[cur][mi], bf[cur][p][0], bf[cur][p][2]);
                    mma_f16(acc[mi][2 * p + 1], af[cur][mi], bf[cur][p][1], bf[cur][p][3]);
                }
        }
        // no end-of-loop sync: next iteration's top sync orders buffer reuse
    }

    // epilogue (register-lean, direct stores)
#pragma unroll
    for (int mi = 0; mi < 4; mi++) {
#pragma unroll
        for (int ni = 0; ni < 8; ni++) {
            int c = col0 + wn + ni * 8 + tig * 2;
            float2 bv = __ldg((const float2*)(bias + c));
#pragma unroll
            for (int h = 0; h < 2; h++) {
                int r = row0 + wm + mi * 16 + gID + h * 8;
                float v0 = acc[mi][ni][h * 2 + 0] + bv.x;
                float v1 = acc[mi][ni][h * 2 + 1] + bv.y;
                if (EPI == 1) {
                    float2 rv = __ldg((const float2*)(res + (size_t)r * ldc + c));
                    v0 += rv.x;
                    v1 += rv.y;
                    *(float2*)((float*)C + (size_t)r * ldc + c) = make_float2(v0, v1);
                } else if (EPI == 2) {
                    __half2 o = __floats2half2_rn(gelu_exact(v0), gelu_exact(v1));
                    *(__half2*)((__half*)C + (size_t)r * ldc + c) = o;
                } else {
                    __half2 o = __floats2half2_rn(v0, v1);
                    *(__half2*)((__half*)C + (size_t)r * ldc + c) = o;
                }
            }
        }
    }
}

// ---------------------------------------------------------------- launch
extern "C" void kernel_launch(void* const* d_in, const int* in_sizes, int n_in,
                              void* d_out, int out_size)
{
    const float* x     = (const float*)d_in[0];
    const float* W_qkv = (const float*)d_in[1];
    const float* b_qkv = (const float*)d_in[2];
    const float* W_out = (const float*)d_in[3];
    const float* b_out = (const float*)d_in[4];
    const float* ln1_g = (const float*)d_in[5];
    const float* ln1_b = (const float*)d_in[6];
    const float* ln2_g = (const float*)d_in[7];
    const float* ln2_b = (const float*)d_in[8];
    const float* W1    = (const float*)d_in[9];
    const float* b1    = (const float*)d_in[10];
    const float* W2    = (const float*)d_in[11];
    const float* b2    = (const float*)d_in[12];
    float* out = (float*)d_out;

    __half *s1, *s2, *w;
    float *xr;
    cudaGetSymbolAddress((void**)&s1, g_s1);
    cudaGetSymbolAddress((void**)&s2, g_s2);
    cudaGetSymbolAddress((void**)&xr, g_xr);
    cudaGetSymbolAddress((void**)&w,  g_w);

    cudaFuncSetAttribute((const void*)hgemm_kernel<0, __half>,
                         cudaFuncAttributeMaxDynamicSharedMemorySize, SMEMG_BYTES);
    cudaFuncSetAttribute((const void*)hgemm_kernel<1, float>,
                         cudaFuncAttributeMaxDynamicSharedMemorySize, SMEMG_BYTES);
    cudaFuncSetAttribute((const void*)hgemm_kernel<2, __half>,
                         cudaFuncAttributeMaxDynamicSharedMemorySize, SMEMG_BYTES);

    // 0) transpose + fp16-round all weights: W[K,N] -> WT[N,K]
    transpose_h_kernel<<<dim3(768 / 32, 256 / 32, 3), dim3(32, 8)>>>(W_qkv, w + WOFF_QKV, 256, 768);
    transpose_h_kernel<<<dim3(256 / 32, 256 / 32, 1), dim3(32, 8)>>>(W_out, w + WOFF_OUT, 256, 256);
    transpose_h_kernel<<<dim3(3072 / 32, 768 / 32, 1), dim3(32, 8)>>>(W1, w + WOFF_W1, 768, 3072);
    transpose_h_kernel<<<dim3(768 / 32, 3072 / 32, 1), dim3(32, 8)>>>(W2, w + WOFF_W2, 3072, 768);

    // 1) LN1: x -> h (s2, half)
    ln_kernel<<<T_TOK / 8, 256>>>(x, ln1_g, ln1_b, s2);

    // 2) QKV (all 3 channels, gridDim.z=3): [32768,256] @ [256,768] -> s1[T,2304]
    hgemm_kernel<0, __half><<<dim3(6, 256, 3), 128, SMEMG_BYTES>>>(
        KFD,
        s2, H_DIM, (size_t)KFD,
        w + WOFF_QKV, KFD, (size_t)768 * 256,
        s1, 2304, (size_t)768,
        b_qkv, (size_t)768,
        nullptr);

    // 3) attention: qkv(s1) -> ctx(s2) [T*3, 256] half
    attn_kernel<<<(T_TOK * 128) / 256, 256>>>(s1, s2);

    // 4) out-proj + residual: [98304,256] @ [256,256] + x -> xr (fp32)
    hgemm_kernel<1, float><<<dim3(2, 768, 1), 128, SMEMG_BYTES>>>(
        KFD, s2, KFD, 0, w + WOFF_OUT, KFD, 0, xr, KFD, 0, b_out, 0, x);

    // 5) LN2: xr -> y (s2, half)
    ln_kernel<<<T_TOK / 8, 256>>>(xr, ln2_g, ln2_b, s2);

    // 6) MLP fc1 + GELU: [32768,768] @ [768,3072] -> act (s1, half)
    hgemm_kernel<2, __half><<<dim3(24, 256, 1), 128, SMEMG_BYTES>>>(
        H_DIM, s2, H_DIM, 0, w + WOFF_W1, H_DIM, 0, s1, M_MLP, 0, b1, 0, nullptr);

    // 7) MLP fc2 + residual: [32768,3072] @ [3072,768] + xr -> out (fp32)
    hgemm_kernel<1, float><<<dim3(6, 256, 1), 128, SMEMG_BYTES>>>(
        M_MLP, s1, M_MLP, 0, w + WOFF_W2, M_MLP, 0, out, H_DIM, 0, b2, 0, xr);
}

// round 14
// speedup vs baseline: 1.5029x; 1.0015x over previous
#include <cuda_runtime.h>
#include <cuda_fp16.h>
#include <math.h>
#include <stdint.h>

#define T_TOK 32768
#define H_DIM 768
#define C_CH  3
#define KFD   256
#define M_MLP 3072
#define LN_EPS 1e-6f

// ---- GEMM tiling (fp16 mma.sync m16n8k16, swizzled smem, ldmatrix) ----
#define GBM 128
#define GBN 128
#define BKH 64                     // halves per K-tile (128B rows)
#define STAGES 3
#define A_BYTES (GBM * 128)        // 16384
#define B_BYTES (GBN * 128)        // 16384
#define STAGE_BYTES (A_BYTES + B_BYTES)     // 32768
#define SMEMG_BYTES (STAGES * STAGE_BYTES)  // 98304

// Scratch (device globals; no allocations anywhere).
__device__ __align__(16) __half g_s1[(size_t)T_TOK * M_MLP];  // qkv [T,2304] then act [T,3072]
__device__ __align__(16) __half g_s2[(size_t)T_TOK * H_DIM];  // h / ctx / y
__device__ __align__(16) float  g_xr[(size_t)T_TOK * H_DIM];
// transposed fp16 weights (K-major rows [N,K]):
#define WOFF_QKV 0
#define WOFF_OUT 589824
#define WOFF_W1  655360
#define WOFF_W2  3014656
__device__ __align__(16) __half g_w[5373952];

// ---------------------------------------------------------------- helpers
__device__ __forceinline__ float gelu_exact(float x)
{
    return 0.5f * x * (1.0f + erff(x * 0.70710678118654752f));
}

__device__ __forceinline__ void cp16(uint32_t dst_smem, const void* src)
{
    asm volatile("cp.async.cg.shared.global [%0], [%1], 16;\n" :: "r"(dst_smem), "l"(src));
}

__device__ __forceinline__ void ldsm4(uint32_t* r, uint32_t addr)
{
    asm volatile("ldmatrix.sync.aligned.m8n8.x4.shared.b16 {%0,%1,%2,%3}, [%4];"
                 : "=r"(r[0]), "=r"(r[1]), "=r"(r[2]), "=r"(r[3]) : "r"(addr));
}

__device__ __forceinline__ void mma_f16(float* d, const uint32_t* a,
                                        uint32_t b0, uint32_t b1)
{
    asm volatile(
        "mma.sync.aligned.m16n8k16.row.col.f32.f16.f16.f32 "
        "{%0,%1,%2,%3}, {%4,%5,%6,%7}, {%8,%9}, {%0,%1,%2,%3};\n"
        : "+f"(d[0]), "+f"(d[1]), "+f"(d[2]), "+f"(d[3])
        : "r"(a[0]), "r"(a[1]), "r"(a[2]), "r"(a[3]), "r"(b0), "r"(b1));
}

// ---------------------------------------------------------------- transpose+half
// One launch for all four weights; blocks dispatched by range.
// seg0 [0,576):    W_qkv  3 x [256,768]  -> [768,256]   (192 tiles / channel)
// seg1 [576,640):  W_out  [256,256]      -> [256,256]
// seg2 [640,2944): W1     [768,3072]     -> [3072,768]
// seg3 [2944,5248):W2     [3072,768]     -> [768,3072]
__device__ __forceinline__ void tr_tile(const float* __restrict__ in,
                                        __half* __restrict__ out,
                                        int K, int N, int k0, int n0)
{
    __shared__ float t[32][33];
    int x = threadIdx.x, y = threadIdx.y;
#pragma unroll
    for (int i = 0; i < 32; i += 8)
        t[y + i][x] = in[(size_t)(k0 + y + i) * N + n0 + x];
    __syncthreads();
#pragma unroll
    for (int i = 0; i < 32; i += 8)
        out[(size_t)(n0 + y + i) * K + k0 + x] = __float2half_rn(t[x][y + i]);
}

__global__ void transpose_all_kernel(const float* __restrict__ Wqkv,
                                     const float* __restrict__ Wout,
                                     const float* __restrict__ W1,
                                     const float* __restrict__ W2,
                                     __half* __restrict__ w)
{
    int b = blockIdx.x;
    if (b < 576) {
        int z = b / 192, t = b % 192;            // 24 x 8 tiles per channel
        int nx = t % 24, ky = t / 24;
        tr_tile(Wqkv + (size_t)z * 256 * 768, w + WOFF_QKV + (size_t)z * 768 * 256,
                256, 768, ky * 32, nx * 32);
    } else if (b < 640) {
        int t = b - 576;                          // 8 x 8 tiles
        int nx = t % 8, ky = t / 8;
        tr_tile(Wout, w + WOFF_OUT, 256, 256, ky * 32, nx * 32);
    } else if (b < 2944) {
        int t = b - 640;                          // 96 x 24 tiles
        int nx = t % 96, ky = t / 96;
        tr_tile(W1, w + WOFF_W1, 768, 3072, ky * 32, nx * 32);
    } else {
        int t = b - 2944;                         // 24 x 96 tiles
        int nx = t % 24, ky = t / 24;
        tr_tile(W2, w + WOFF_W2, 3072, 768, ky * 32, nx * 32);
    }
}

// ---------------------------------------------------------------- LayerNorm -> half
// vectorized: float4 loads, 16B (half2 x2) stores
__global__ void ln_kernel(const float* __restrict__ in,
                          const float* __restrict__ gam,
                          const float* __restrict__ bet,
                          __half* __restrict__ out)
{
    int gwarp = (blockIdx.x * blockDim.x + threadIdx.x) >> 5;
    int lane  = threadIdx.x & 31;
    if (gwarp >= T_TOK) return;
    const float4* row = (const float4*)(in + (size_t)gwarp * H_DIM);
    float4 v[6];
    float s = 0.f, sq = 0.f;
#pragma unroll
    for (int i = 0; i < 6; i++) {
        v[i] = row[lane + 32 * i];
        s  += v[i].x + v[i].y + v[i].z + v[i].w;
        sq += v[i].x * v[i].x + v[i].y * v[i].y + v[i].z * v[i].z + v[i].w * v[i].w;
    }
#pragma unroll
    for (int o = 16; o > 0; o >>= 1) {
        s  += __shfl_xor_sync(0xffffffffu, s,  o);
        sq += __shfl_xor_sync(0xffffffffu, sq, o);
    }
    float mu  = s * (1.0f / H_DIM);
    float var = fmaxf(sq * (1.0f / H_DIM) - mu * mu, 0.0f);
    float rs  = rsqrtf(var + LN_EPS);
    __half* orow = out + (size_t)gwarp * H_DIM;
#pragma unroll
    for (int i = 0; i < 6; i++) {
        int j4 = lane + 32 * i;
        float4 g = *(const float4*)(gam + j4 * 4);
        float4 b = *(const float4*)(bet + j4 * 4);
        float o0 = (v[i].x - mu) * rs * g.x + b.x;
        float o1 = (v[i].y - mu) * rs * g.y + b.y;
        float o2 = (v[i].z - mu) * rs * g.z + b.z;
        float o3 = (v[i].w - mu) * rs * g.w + b.w;
        uint2 pk;
        ((__half2*)&pk.x)[0] = __floats2half2_rn(o0, o1);
        ((__half2*)&pk.y)[0] = __floats2half2_rn(o2, o3);
        *(uint2*)(orow + j4 * 4) = pk;
    }
}

// ------------------------------------------------- criss-cross attention core
// half2-vectorized: each thread handles 2 adjacent kf
__global__ void attn_kernel(const __half* __restrict__ qkv, __half* __restrict__ ctx)
{
    int gid = blockIdx.x * blockDim.x + threadIdx.x; // t*128 + p
    int t  = gid >> 7;
    int p  = (gid & 127) * 2;
    const __half* base = qkv + (size_t)t * (3 * H_DIM);
    float2 q[3], k[3], v[3];
#pragma unroll
    for (int c = 0; c < 3; c++) {
        q[c] = __half22float2(*(const __half2*)(base + c * H_DIM + p));
        k[c] = __half22float2(*(const __half2*)(base + c * H_DIM + KFD + p));
        v[c] = __half22float2(*(const __half2*)(base + c * H_DIM + 2 * KFD + p));
    }
    const float scale = 0.0625f;
    float o0x = 0.f, o1x = 0.f, o2x = 0.f;
    float o0y = 0.f, o1y = 0.f, o2y = 0.f;
#pragma unroll
    for (int c = 0; c < 3; c++) {
        {
            float s0 = q[c].x * k[0].x * scale;
            float s1 = q[c].x * k[1].x * scale;
            float s2 = q[c].x * k[2].x * scale;
            float m  = fmaxf(s0, fmaxf(s1, s2));
            float e0 = __expf(s0 - m), e1 = __expf(s1 - m), e2 = __expf(s2 - m);
            float inv = v[c].x / (e0 + e1 + e2);
            o0x = fmaf(e0, inv, o0x);
            o1x = fmaf(e1, inv, o1x);
            o2x = fmaf(e2, inv, o2x);
        }
        {
            float s0 = q[c].y * k[0].y * scale;
            float s1 = q[c].y * k[1].y * scale;
            float s2 = q[c].y * k[2].y * scale;
            float m  = fmaxf(s0, fmaxf(s1, s2));
            float e0 = __expf(s0 - m), e1 = __expf(s1 - m), e2 = __expf(s2 - m);
            float inv = v[c].y / (e0 + e1 + e2);
            o0y = fmaf(e0, inv, o0y);
            o1y = fmaf(e1, inv, o1y);
            o2y = fmaf(e2, inv, o2y);
        }
    }
    __half* ob = ctx + (size_t)t * 3 * KFD + p;
    *(__half2*)(ob)           = __floats2half2_rn(o0x, o0y);
    *(__half2*)(ob + KFD)     = __floats2half2_rn(o1x, o1y);
    *(__half2*)(ob + 2 * KFD) = __floats2half2_rn(o2x, o2y);
}

// ---------------------------------------------------------------- FP16 GEMM
// C[M,N] = A[M,K] @ BT[N,K]^T (+bias / +bias+res / gelu(+bias))
// CTA 128x128, 128 threads (4 warps, 2x2 of 64x64), 3-stage cp.async,
// 96KB smem -> 2 CTAs/SM. SW128-swizzled rows, ldmatrix, frag double-buffer.
// Single sync per K-tile; copies issued after step-0 MMAs (tensor-first order).
template <int EPI, typename TO>
__global__ void __launch_bounds__(128, 2)
hgemm_kernel(int K,
             const __half* __restrict__ A, int lda, size_t az,
             const __half* __restrict__ BT, int ldb, size_t bz,
             TO* __restrict__ C, int ldc, size_t cz,
             const float* __restrict__ bias, size_t biasz,
             const float* __restrict__ res)
{
    extern __shared__ char smem[];
    const uint32_t sbase = (uint32_t)__cvta_generic_to_shared(smem);

    const int tid  = threadIdx.x;
    const int wid  = tid >> 5;
    const int lane = tid & 31;
    const int gID  = lane >> 2;
    const int tig  = lane & 3;
    const int wm   = (wid >> 1) * 64;
    const int wn   = (wid & 1) * 64;
    const int row0 = blockIdx.y * GBM;
    const int col0 = blockIdx.x * GBN;

    A    += (size_t)blockIdx.z * az;
    BT   += (size_t)blockIdx.z * bz;
    C    += (size_t)blockIdx.z * cz;
    bias += (size_t)blockIdx.z * biasz;

    const __half* Ag = A + (size_t)row0 * lda;
    const __half* Bg = BT + (size_t)col0 * ldb;

    // copy mapping: 128 threads, A: 8 chunks/thread, B: 8 chunks/thread
    const int cr = tid >> 3;          // 0..15
    const int cc = tid & 7;           // logical 16B chunk

    // ldmatrix lane geometry
    const int lrA = wm + (lane & 15);
    const int lrB = wn + (lane & 15);
    const int hi  = lane >> 4;
    const int sxA = lrA & 7;
    const int sxB = lrB & 7;

    float acc[4][8][4];
#pragma unroll
    for (int mi = 0; mi < 4; mi++)
#pragma unroll
        for (int ni = 0; ni < 8; ni++)
#pragma unroll
            for (int j = 0; j < 4; j++) acc[mi][ni][j] = 0.f;

    const int nk = K / BKH;

    // prologue
#pragma unroll
    for (int s = 0; s < STAGES - 1; s++) {
        if (s < nk) {
            uint32_t as = sbase + s * STAGE_BYTES;
            uint32_t bs = as + A_BYTES;
            int k0 = s * BKH;
#pragma unroll
            for (int i = 0; i < 8; i++) {
                int r = cr + 16 * i, c = cc;
                cp16(as + r * 128 + ((c ^ (r & 7)) << 4),
                     Ag + (size_t)r * lda + k0 + c * 8);
                cp16(bs + r * 128 + ((c ^ (r & 7)) << 4),
                     Bg + (size_t)r * ldb + k0 + c * 8);
            }
        }
        asm volatile("cp.async.commit_group;\n");
    }

    for (int kt = 0; kt < nk; kt++) {
        asm volatile("cp.async.wait_group %0;\n" :: "n"(STAGES - 2));
        __syncthreads();

        const uint32_t abase = sbase + (kt % STAGES) * STAGE_BYTES + lrA * 128;
        const uint32_t bbase = sbase + (kt % STAGES) * STAGE_BYTES + A_BYTES + lrB * 128;

        uint32_t af[2][4][4], bf[2][4][4];
        // fragments for k-step 0 first: tensor work starts ASAP
        {
            uint32_t chA = (uint32_t)((hi ^ sxA) << 4);
            uint32_t chB = (uint32_t)((hi ^ sxB) << 4);
#pragma unroll
            for (int mi = 0; mi < 4; mi++) ldsm4(af[0][mi], abase + mi * 2048 + chA);
#pragma unroll
            for (int p = 0; p < 4; p++) ldsm4(bf[0][p], bbase + p * 2048 + chB);
        }
#pragma unroll
        for (int s = 0; s < 4; s++) {
            int cur = s & 1, nxt = cur ^ 1;
            if (s == 1) {
                // issue next-stage copies after step-0 MMAs are in flight
                int kf = kt + STAGES - 1;
                if (kf < nk) {
                    uint32_t as = sbase + (kf % STAGES) * STAGE_BYTES;
                    uint32_t bs = as + A_BYTES;
                    int k0 = kf * BKH;
#pragma unroll
                    for (int i = 0; i < 8; i++) {
                        int r = cr + 16 * i, c = cc;
                        cp16(as + r * 128 + ((c ^ (r & 7)) << 4),
                             Ag + (size_t)r * lda + k0 + c * 8);
                        cp16(bs + r * 128 + ((c ^ (r & 7)) << 4),
                             Bg + (size_t)r * ldb + k0 + c * 8);
                    }
                }
                asm volatile("cp.async.commit_group;\n");
            }
            if (s < 3) {
                uint32_t chA = (uint32_t)(((2 * (s + 1) + hi) ^ sxA) << 4);
                uint32_t chB = (uint32_t)(((2 * (s + 1) + hi) ^ sxB) << 4);
#pragma unroll
                for (int mi = 0; mi < 4; mi++) ldsm4(af[nxt][mi], abase + mi * 2048 + chA);
#pragma unroll
                for (int p = 0; p < 4; p++) ldsm4(bf[nxt][p], bbase + p * 2048 + chB);
            }
#pragma unroll
            for (int mi = 0; mi < 4; mi++)
#pragma unroll
                for (int p = 0; p < 4; p++) {
                    mma_f16(acc[mi][2 * p],     af[cur][mi], bf[cur][p][0], bf[cur][p][2]);
                    mma_f16(acc[mi][2 * p + 1], af[cur][mi], bf[cur][p][1], bf[cur][p][3]);
                }
        }
        // no end-of-loop sync: next iteration's top sync orders buffer reuse
    }

    // epilogue (register-lean, direct stores)
#pragma unroll
    for (int mi = 0; mi < 4; mi++) {
#pragma unroll
        for (int ni = 0; ni < 8; ni++) {
            int c = col0 + wn + ni * 8 + tig * 2;
            float2 bv = __ldg((const float2*)(bias + c));
#pragma unroll
            for (int h = 0; h < 2; h++) {
                int r = row0 + wm + mi * 16 + gID + h * 8;
                float v0 = acc[mi][ni][h * 2 + 0] + bv.x;
                float v1 = acc[mi][ni][h * 2 + 1] + bv.y;
                if (EPI == 1) {
                    float2 rv = __ldg((const float2*)(res + (size_t)r * ldc + c));
                    v0 += rv.x;
                    v1 += rv.y;
                    *(float2*)((float*)C + (size_t)r * ldc + c) = make_float2(v0, v1);
                } else if (EPI == 2) {
                    __half2 o = __floats2half2_rn(gelu_exact(v0), gelu_exact(v1));
                    *(__half2*)((__half*)C + (size_t)r * ldc + c) = o;
                } else {
                    __half2 o = __floats2half2_rn(v0, v1);
                    *(__half2*)((__half*)C + (size_t)r * ldc + c) = o;
                }
            }
        }
    }
}

// ---------------------------------------------------------------- launch
extern "C" void kernel_launch(void* const* d_in, const int* in_sizes, int n_in,
                              void* d_out, int out_size)
{
    const float* x     = (const float*)d_in[0];
    const float* W_qkv = (const float*)d_in[1];
    const float* b_qkv = (const float*)d_in[2];
    const float* W_out = (const float*)d_in[3];
    const float* b_out = (const float*)d_in[4];
    const float* ln1_g = (const float*)d_in[5];
    const float* ln1_b = (const float*)d_in[6];
    const float* ln2_g = (const float*)d_in[7];
    const float* ln2_b = (const float*)d_in[8];
    const float* W1    = (const float*)d_in[9];
    const float* b1    = (const float*)d_in[10];
    const float* W2    = (const float*)d_in[11];
    const float* b2    = (const float*)d_in[12];
    float* out = (float*)d_out;

    __half *s1, *s2, *w;
    float *xr;
    cudaGetSymbolAddress((void**)&s1, g_s1);
    cudaGetSymbolAddress((void**)&s2, g_s2);
    cudaGetSymbolAddress((void**)&xr, g_xr);
    cudaGetSymbolAddress((void**)&w,  g_w);

    cudaFuncSetAttribute((const void*)hgemm_kernel<0, __half>,
                         cudaFuncAttributeMaxDynamicSharedMemorySize, SMEMG_BYTES);
    cudaFuncSetAttribute((const void*)hgemm_kernel<1, float>,
                         cudaFuncAttributeMaxDynamicSharedMemorySize, SMEMG_BYTES);
    cudaFuncSetAttribute((const void*)hgemm_kernel<2, __half>,
                         cudaFuncAttributeMaxDynamicSharedMemorySize, SMEMG_BYTES);

    // 0) transpose + fp16-round all weights in ONE launch: W[K,N] -> WT[N,K]
    transpose_all_kernel<<<5248, dim3(32, 8)>>>(W_qkv, W_out, W1, W2, w);

    // 1) LN1: x -> h (s2, half)
    ln_kernel<<<T_TOK / 8, 256>>>(x, ln1_g, ln1_b, s2);

    // 2) QKV (all 3 channels, gridDim.z=3): [32768,256] @ [256,768] -> s1[T,2304]
    hgemm_kernel<0, __half><<<dim3(6, 256, 3), 128, SMEMG_BYTES>>>(
        KFD,
        s2, H_DIM, (size_t)KFD,
        w + WOFF_QKV, KFD, (size_t)768 * 256,
        s1, 2304, (size_t)768,
        b_qkv, (size_t)768,
        nullptr);

    // 3) attention: qkv(s1) -> ctx(s2) [T*3, 256] half
    attn_kernel<<<(T_TOK * 128) / 256, 256>>>(s1, s2);

    // 4) out-proj + residual: [98304,256] @ [256,256] + x -> xr (fp32)
    hgemm_kernel<1, float><<<dim3(2, 768, 1), 128, SMEMG_BYTES>>>(
        KFD, s2, KFD, 0, w + WOFF_OUT, KFD, 0, xr, KFD, 0, b_out, 0, x);

    // 5) LN2: xr -> y (s2, half)
    ln_kernel<<<T_TOK / 8, 256>>>(xr, ln2_g, ln2_b, s2);

    // 6) MLP fc1 + GELU: [32768,768] @ [768,3072] -> act (s1, half)
    hgemm_kernel<2, __half><<<dim3(24, 256, 1), 128, SMEMG_BYTES>>>(
        H_DIM, s2, H_DIM, 0, w + WOFF_W1, H_DIM, 0, s1, M_MLP, 0, b1, 0, nullptr);

    // 7) MLP fc2 + residual: [32768,3072] @ [3072,768] + xr -> out (fp32)
    hgemm_kernel<1, float><<<dim3(6, 256, 1), 128, SMEMG_BYTES>>>(
        M_MLP, s1, M_MLP, 0, w + WOFF_W2, M_MLP, 0, out, H_DIM, 0, b2, 0, xr);
}